// round 10
// baseline (speedup 1.0000x reference)
#include <cuda_runtime.h>
#include <math.h>

#define BATCH   64
#define NLIST   512
#define THREADS 512
#define NBLK    128            // 2 blocks per row = 1 cluster per row

#define LOG_EPS (-23.025850929940457f)
#define LN2F    0.6931471805599453f

// 1/log1p(k) for k=0..52 (k=0 unused)
__constant__ float C_IL[53] = {
    0.0f,        1.44269504f, 0.91023923f, 0.72134752f, 0.62133493f,
    0.55811063f, 0.51389834f, 0.48089835f, 0.45511961f, 0.43429448f,
    0.41703239f, 0.40242960f, 0.38987124f, 0.37892269f, 0.36926938f,
    0.36067376f, 0.35295525f, 0.34597526f, 0.33962297f, 0.33380821f,
    0.32845724f, 0.32351538f, 0.31892891f, 0.31465802f, 0.31066747f,
    0.30692762f, 0.30341308f, 0.30010212f, 0.29697521f, 0.29401538f,
    0.29120814f, 0.28853901f, 0.28599983f, 0.28357871f, 0.28126653f,
    0.27905531f, 0.27693789f, 0.27490773f, 0.27295812f, 0.27108450f,
    0.26928330f, 0.26754748f, 0.26587369f, 0.26425870f, 0.26269878f,
    0.26119069f, 0.25973142f, 0.25831873f, 0.25694924f, 0.25562222f,
    0.25433417f, 0.25308478f, 0.25187249f
};

__device__ float        g_partial[NBLK];
__device__ unsigned int g_count = 0;

__global__ __launch_bounds__(THREADS, 1) __cluster_dims__(2, 1, 1)
void rank_loss_main(const float* __restrict__ logits,
                    const float* __restrict__ labels,
                    float* __restrict__ out) {
    __shared__ float  s_sl[NLIST];        // masked logits (rank phase)
    __shared__ float4 sA[NLIST + 256];    // {Gj, Ej, hj, labj(NaN invalid)} + mirror
    __shared__ float  sBp[NLIST + 256];   // qd with capped in low 8 mantissa bits + mirror
    __shared__ int    s_cnt[THREADS];     // partial rank counts
    __shared__ __align__(4) unsigned char sC[NLIST];  // capped ranks (cluster-shared)
    __shared__ float  s_rel[103 * 32];    // symmetric replicated: [d*32+lane], d=ci-cj+51
    __shared__ float  s_red[16];
    __shared__ bool   s_last;

    const int tid  = threadIdx.x;
    const int lane = tid & 31;
    const int b    = blockIdx.x >> 1;
    const int h    = blockIdx.x & 1;      // == cluster ctarank

    // --- symmetric replicated rel LUT from constant literals ---
    for (int idx = tid; idx < 103 * 32; idx += THREADS) {
        const int d = idx >> 5;
        const int k = abs(d - 51);
        s_rel[idx] = k ? 0.75f * fabsf(C_IL[k] - C_IL[k + 1]) : 0.0f;
    }

    // --- per-element load / masking / sA fill ---
    const float gr    = logits[b * NLIST + tid];
    const float lr    = labels[b * NLIST + tid];
    const bool  valid = lr > -1000.0f;
    const float lab   = valid ? lr : 0.0f;
    const float g     = valid ? gr : LOG_EPS;
    s_sl[tid] = g;

    const float Gi   = __expf(0.5f * g);    // exp(logit/2)
    const float Ei   = __expf(0.5f * lab);  // exp(label/2)
    const float hi   = 0.5f * g;
    const float nhi  = -hi;
    const float qnan = __int_as_float(0x7fffffff);
    const float labi = valid ? lab : qnan;  // NaN sentinel -> pair inactive

    const float4 Av = make_float4(Gi, Ei, hi, labi);
    sA[tid] = Av;
    if (tid < 256) sA[NLIST + tid] = Av;
    __syncthreads();

    // --- split rank scan: this CTA ranks its 256 elements, 2 threads/element ---
    const int   el = (h << 8) + (tid & 255);
    const int   jh = tid >> 8;
    const float ge = s_sl[el];
    int c0 = 0, c1 = 0, c2 = 0, c3 = 0;
    const float4* p4 = (const float4*)(s_sl + (jh << 8));
    #pragma unroll 8
    for (int k = 0; k < 64; ++k) {
        float4 v = p4[k];                  // uniform addr -> broadcast
        c0 += (v.x > ge);
        c1 += (v.y > ge);
        c2 += (v.z > ge);
        c3 += (v.w > ge);
    }
    s_cnt[tid] = c0 + c1 + c2 + c3;
    __syncthreads();

    if (tid < 256) {
        const int cnt = s_cnt[tid] + s_cnt[tid + 256];
        // ties only among the invalid cluster (all at LOG_EPS): capped=51 either
        // way and such elements appear only in masked pairs -> plain '>' exact
        sC[el] = (unsigned char)min(cnt + 1, 51);
    }
    __syncthreads();

    // --- DSMEM exchange: push our 256 capped bytes into peer CTA's sC ---
    if (tid < 64) {
        const int off = (h << 8) + (tid << 2);
        const unsigned w32   = *(const unsigned*)&sC[off];
        const unsigned laddr = (unsigned)__cvta_generic_to_shared(&sC[off]);
        unsigned paddr;
        asm("mapa.shared::cluster.u32 %0, %1, %2;"
            : "=r"(paddr) : "r"(laddr), "r"(h ^ 1));
        asm volatile("st.shared::cluster.u32 [%0], %1;"
                     :: "r"(paddr), "r"(w32) : "memory");
    }
    asm volatile("barrier.cluster.arrive.aligned;" ::: "memory");
    asm volatile("barrier.cluster.wait.aligned;" ::: "memory");

    // --- per-element qd + pack (capped in low 8 mantissa bits of qd) ---
    const int   capped = sC[tid];
    const float qdi    = (capped <= 50) ? 0.25f * C_IL[capped] : 0.0f;
    const unsigned qbits = (__float_as_uint(qdi) & ~0xFFu) | (unsigned)capped;
    sBp[tid] = __uint_as_float(qbits);
    if (tid < 256) sBp[NLIST + tid] = __uint_as_float(qbits);
    __syncthreads();

    // --- per-row IDCG (thread 0) ---
    float idcg = 0.0f;
    if (tid == 0) {
        float s = 0.0f;
        #pragma unroll
        for (int p = 1; p <= 50; ++p)
            if (sA[p - 1].w < 1e30f) s += C_IL[p];   // NaN compare -> false
        idcg = (s > 0.0f) ? (1.0f / s) : 0.0f;
    }

    // --- pair loop: orientation-free identity (exact for both directions):
    //     bce = ln2*lg2(Gi+Gj) - hi + dh*Ej/(Ei+Ej),  dh = hi-hj
    //     w = rel[ci-cj+51] + 0.25|di-dj|;  mask |labi-labj|>0 (NaN-safe, predicated) ---
    const float*  relb = s_rel + ((capped + 51) << 5) + lane;
    const float4* pA   = sA  + tid + 1 + (h << 7);
    const float*  pB   = sBp + tid + 1 + (h << 7);

    auto body = [&](const float4 A, const float Bp, float& acc) {
        const float t2  = __fdividef(A.y, Ei + A.y);
        const float lg  = __log2f(Gi + A.x);
        const float dh  = hi - A.z;
        const float bce = fmaf(dh, t2, fmaf(lg, LN2F, nhi));
        const float dl  = labi - A.w;                 // NaN if either invalid
        const int   cj  = (int)(__float_as_uint(Bp) & 0xFFu);
        const float w   = relb[-(cj << 5)] + fabsf(qdi - Bp);
        if (fabsf(dl) > 0.0f) acc = fmaf(bce, w, acc);   // predicated FFMA
    };

    float a0 = 0.0f, a1 = 0.0f, a2 = 0.0f, a3 = 0.0f, a4 = 0.0f, a5 = 0.0f;
    int oo = 0;
    // 6-wide staged batches: 12 LDS in flight, 6 independent chains (offsets 0..125)
    for (; oo + 6 <= 126; oo += 6) {
        const float4 A0 = pA[oo],     A1 = pA[oo + 1], A2 = pA[oo + 2];
        const float4 A3 = pA[oo + 3], A4 = pA[oo + 4], A5 = pA[oo + 5];
        const float  B0 = pB[oo],     B1 = pB[oo + 1], B2 = pB[oo + 2];
        const float  B3 = pB[oo + 3], B4 = pB[oo + 4], B5 = pB[oo + 5];
        body(A0, B0, a0);
        body(A1, B1, a1);
        body(A2, B2, a2);
        body(A3, B3, a3);
        body(A4, B4, a4);
        body(A5, B5, a5);
    }
    body(pA[126], pB[126], a0);           // offset 126
    {   // final offset (128 or 256); offset 256 double-covered -> gate tid<256
        const bool gate = (h == 0) | (tid < 256);
        float av = 0.0f;
        body(pA[127], pB[127], av);
        a1 += gate ? av : 0.0f;
    }
    float acc = ((a0 + a1) + (a2 + a3)) + (a4 + a5);

    // --- deterministic block reduce + fused final reduce ---
    #pragma unroll
    for (int o = 16; o; o >>= 1) acc += __shfl_down_sync(0xffffffffu, acc, o);
    if (lane == 0) s_red[tid >> 5] = acc;
    __syncthreads();
    if (tid < 16) {
        float v = s_red[tid];
        #pragma unroll
        for (int o = 8; o; o >>= 1) v += __shfl_down_sync(0xffffu, v, o);
        if (tid == 0) {
            g_partial[blockIdx.x] = v * idcg * (1.0f / (float)BATCH);
            __threadfence();
            unsigned int old = atomicInc(&g_count, NBLK - 1);  // wraps -> replay-safe
            s_last = (old == NBLK - 1);
        }
    }
    __syncthreads();

    if (s_last) {
        __threadfence();
        if (tid < NBLK) {
            float v = ((volatile float*)g_partial)[tid];
            #pragma unroll
            for (int o = 16; o; o >>= 1) v += __shfl_down_sync(0xffffffffu, v, o);
            if (lane == 0) s_red[tid >> 5] = v;
        }
        __syncthreads();
        if (tid == 0) {
            float tot = 0.0f;
            #pragma unroll
            for (int w2 = 0; w2 < NBLK / 32; ++w2) tot += s_red[w2];
            out[0] = tot;
        }
    }
}

extern "C" void kernel_launch(void* const* d_in, const int* in_sizes, int n_in,
                              void* d_out, int out_size) {
    const float* logits = (const float*)d_in[0];
    const float* labels = (const float*)d_in[1];
    float* out = (float*)d_out;
    (void)in_sizes; (void)n_in; (void)out_size;

    rank_loss_main<<<NBLK, THREADS>>>(logits, labels, out);
}